// round 11
// baseline (speedup 1.0000x reference)
#include <cuda_runtime.h>
#include <math.h>
#include <stdint.h>

// Problem constants
#define HW      262144        // 512*512
#define NTILES  16384         // 2M pixels / 128-pixel tiles
#define GRID1   296           // 2 CTAs per SM
#define K       19
#define KC      1216          // 19*64

// Scratch (no allocation allowed -> __device__ globals)
__device__ float g_psums[GRID1 * KC];
__device__ int   g_pcnts[K * GRID1];     // [class][block]
__device__ float g_sums[KC];
__device__ int   g_cnt[K];

// K1 smem layout (bytes). Channel row padded 512->528 B: LDS.128 octet index
// becomes (ca + u) & 7 -> conflict-free with NO swizzle -> linear bulk copies OK.
#define ROWB     528
#define STAGE_B  (64*ROWB + 1024)        // data rows + labels area = 34816
#define NST      3
#define SM_FULL  (NST*STAGE_B)           // 104448: full mbarriers [3]
#define SM_EMPTY (SM_FULL + 24)          // empty mbarriers [3]
#define SM_SHIFT (SM_EMPTY + 24)         // dtype shift word
#define SMEM_BYTES (SM_SHIFT + 64)

__device__ __forceinline__ uint32_t s2u(const void* p) {
    uint32_t a;
    asm("{ .reg .u64 t; cvta.to.shared.u64 t, %1; cvt.u32.u64 %0, t; }" : "=r"(a) : "l"(p));
    return a;
}
#define MBINIT(a,c)   asm volatile("mbarrier.init.shared.b64 [%0], %1;" :: "r"(a), "r"(c) : "memory")
#define MBEXPECT(a,t) asm volatile("mbarrier.arrive.expect_tx.shared.b64 _, [%0], %1;" :: "r"(a), "r"(t) : "memory")
#define MBARRIVE(a)   asm volatile("mbarrier.arrive.shared.b64 _, [%0];" :: "r"(a) : "memory")
#define MBWAIT(a,p) do { unsigned _d = 0; while (!_d) { \
    asm volatile("{\n\t.reg .pred P;\n\t" \
        "mbarrier.try_wait.parity.acquire.cta.shared::cta.b64 P, [%1], %2, 0x989680;\n\t" \
        "selp.b32 %0, 1, 0, P;\n\t}" : "=r"(_d) : "r"(a), "r"(p) : "memory"); } } while (0)
#define BULK(d,s,n,mb) asm volatile( \
    "cp.async.bulk.shared::cluster.global.mbarrier::complete_tx::bytes [%0], [%1], %2, [%3];" \
    :: "r"(d), "l"(s), "r"(n), "r"(mb) : "memory")

// ---------------------------------------------------------------------------
// K1: bulk-async producer + class-owned register-accumulating consumers.
//   warp 19 (producer): per tile, 64x 512B cp.async.bulk (channel rows) +
//     1 labels copy into 3-stage ring; mbarrier expect_tx completion.
//   warps 0..18 (consumers): wait full; lane u parses quad u's 4 labels,
//     ballot -> quad mask, shfl 4-bit match bits; per matching quad
//     2x LDS.128 + predicated FADDs into register accumulators; arrive empty.
// ---------------------------------------------------------------------------
__global__ __launch_bounds__(640, 2) void k1_kernel(const float* __restrict__ inp,
                                                    const int* __restrict__ tgt32) {
    extern __shared__ __align__(16) char smc[];
    const uint32_t base = s2u(smc);
    const int tid = threadIdx.x, lane = tid & 31, wid = tid >> 5, bid = blockIdx.x;
    const int nblk = (NTILES - bid + GRID1 - 1) / GRID1;

    if (tid == 0) {
        #pragma unroll
        for (int s = 0; s < NST; ++s) {
            MBINIT(base + SM_FULL + 8 * s, 1);     // expect_tx arrive only
            MBINIT(base + SM_EMPTY + 8 * s, 608);  // all consumer lanes arrive
        }
    }
    if (wid == 19 && lane == 0) {   // dtype detect: int64 labels have zero high words
        int all0 = 1;
        #pragma unroll
        for (int i = 0; i < 32; ++i)
            if (tgt32[2 * i + 1] != 0) all0 = 0;
        *(int*)(smc + SM_SHIFT) = all0;
    }
    __syncthreads();
    const int shift = *(const int*)(smc + SM_SHIFT);

    if (wid == 19) {
        // ================= PRODUCER WARP =================
        const uint32_t lbytes = 512u << shift;
        const uint32_t tx = 32768u + lbytes;
        int s = 0, m = 0;
        for (int j = 0; j < nblk; ++j) {
            const uint32_t stg = base + s * STAGE_B;
            const uint32_t fb = base + SM_FULL + 8 * s;
            if (j >= NST && lane == 0) MBWAIT(base + SM_EMPTY + 8 * s, (m & 1) ^ 1);
            __syncwarp();
            if (lane == 0) MBEXPECT(fb, tx);
            __syncwarp();
            const int t = bid + j * GRID1;
            const int b = t >> 11, hw0 = (t & 2047) << 7;
            const float* src = inp + ((size_t)b << 24) + hw0 + (size_t)lane * HW;
            BULK(stg + lane * ROWB,        src,                    512u, fb);
            BULK(stg + (lane + 32) * ROWB, src + (size_t)32 * HW,  512u, fb);
            if (lane == 0) {
                const char* lsrc = (const char*)tgt32 +
                                   ((size_t)((b << 18) + hw0) << (2 + shift));
                BULK(stg + 64 * ROWB, lsrc, lbytes, fb);
            }
            if (++s == NST) { s = 0; ++m; }
        }
    } else {
        // ================= CONSUMER WARPS (class wid) =================
        float al = 0.f, al2 = 0.f, ah = 0.f, ah2 = 0.f;
        int ccnt = 0;
        int s = 0, m = 0;
        const int ca = lane;
        for (int j = 0; j < nblk; ++j) {
            const char* sp = smc + s * STAGE_B;
            MBWAIT(base + SM_FULL + 8 * s, m & 1);
            // parse labels for quad u = lane
            int l0, l1, l2, l3;
            if (!shift) {
                int4 L = *(const int4*)(sp + 64 * ROWB + lane * 16);
                l0 = L.x; l1 = L.y; l2 = L.z; l3 = L.w;
            } else {
                int4 A = *(const int4*)(sp + 64 * ROWB + lane * 32);
                int4 B = *(const int4*)(sp + 64 * ROWB + lane * 32 + 16);
                l0 = A.x; l1 = A.z; l2 = B.x; l3 = B.z;
            }
            const int e0 = (l0 == wid), e1 = (l1 == wid), e2 = (l2 == wid), e3 = (l3 == wid);
            const int mb = e0 | (e1 << 1) | (e2 << 2) | (e3 << 3);
            unsigned msk = __ballot_sync(0xffffffffu, mb != 0);
            ccnt += __reduce_add_sync(0xffffffffu, e0 + e1 + e2 + e3);
            const float* rlo = (const float*)(sp + ca * ROWB);
            const float* rhi = (const float*)(sp + (ca + 32) * ROWB);
            while (msk) {
                const int u = __ffs(msk) - 1; msk &= msk - 1;
                float4 flo = *(const float4*)(rlo + u * 4);
                float4 fhi = *(const float4*)(rhi + u * 4);
                const int m4 = __shfl_sync(0xffffffffu, mb, u);
                if (m4 & 1) { al  += flo.x; ah  += fhi.x; }
                if (m4 & 2) { al2 += flo.y; ah2 += fhi.y; }
                if (m4 & 4) { al  += flo.z; ah  += fhi.z; }
                if (m4 & 8) { al2 += flo.w; ah2 += fhi.w; }
            }
            MBARRIVE(base + SM_EMPTY + 8 * s);   // release: orders this lane's reads
            if (++s == NST) { s = 0; ++m; }
        }
        g_psums[bid * KC + (wid << 6) + ca]      = al + al2;
        g_psums[bid * KC + (wid << 6) + 32 + ca] = ah + ah2;
        if (lane == 0) g_pcnts[wid * GRID1 + bid] = ccnt;
    }
}

// ---------------------------------------------------------------------------
// K2: wide psums reduce + counts. Blocks 0..151: 2 float4-columns each,
// 128 threads/column, coalesced rows + smem tree. Block 152: count reduce.
// ---------------------------------------------------------------------------
__global__ __launch_bounds__(256) void k2_kernel() {
    const int tid = threadIdx.x;
    if (blockIdx.x == 152) {      // counts: 8 warps over 19 classes
        const int wid = tid >> 5, lane = tid & 31;
        for (int cls = wid; cls < K; cls += 8) {
            int s = 0;
            for (int p = lane; p < GRID1; p += 32) s += g_pcnts[cls * GRID1 + p];
            #pragma unroll
            for (int off = 16; off > 0; off >>= 1) s += __shfl_xor_sync(0xffffffffu, s, off);
            if (lane == 0) g_cnt[cls] = s;
        }
        return;
    }
    __shared__ float4 red[256];
    const int half = tid >> 7;
    const int r    = tid & 127;
    const int col  = (blockIdx.x << 1) + half; // 0..303
    const float4* ps = (const float4*)g_psums;
    float4 s = make_float4(0.f, 0.f, 0.f, 0.f);
    for (int row = r; row < GRID1; row += 128) {
        float4 v = ps[row * 304 + col];
        s.x += v.x; s.y += v.y; s.z += v.z; s.w += v.w;
    }
    red[tid] = s;
    __syncthreads();
    #pragma unroll
    for (int off = 64; off > 0; off >>= 1) {
        if (r < off) {
            float4 o = red[tid + off];
            s.x += o.x; s.y += o.y; s.z += o.z; s.w += o.w;
            red[tid] = s;
        }
        __syncthreads();
    }
    if (r == 0) ((float4*)g_sums)[col] = red[half << 7];
}

// ---------------------------------------------------------------------------
// K3: centroids + norms (warp-per-class) + cosine-embedding loss. 1 block.
// ---------------------------------------------------------------------------
__global__ __launch_bounds__(640) void k3_kernel(float* __restrict__ out) {
    __shared__ float cen[KC];
    __shared__ float nrm[K];
    __shared__ int   cnts[K];
    __shared__ float red[512];
    const int tid = threadIdx.x;
    const int wid = tid >> 5, lane = tid & 31;

    if (tid < K) cnts[tid] = g_cnt[tid];
    __syncthreads();
    if (tid < 304) {
        float inv = 1.0f / fmaxf((float)cnts[tid >> 4], 1.0f);
        float4 v = ((const float4*)g_sums)[tid];
        ((float4*)cen)[tid] = make_float4(v.x * inv, v.y * inv, v.z * inv, v.w * inv);
    }
    __syncthreads();
    if (wid < K) {
        float x0 = cen[(wid << 6) + lane], x1 = cen[(wid << 6) + 32 + lane];
        float nn = x0 * x0 + x1 * x1;
        #pragma unroll
        for (int off = 16; off > 0; off >>= 1) nn += __shfl_xor_sync(0xffffffffu, nn, off);
        if (lane == 0) nrm[wid] = fmaxf(sqrtf(nn), 1e-8f);
    }
    __syncthreads();
    if (tid < 304) {
        float inv = 1.0f / nrm[tid >> 4];
        float4 v = ((const float4*)cen)[tid];
        ((float4*)cen)[tid] = make_float4(v.x * inv, v.y * inv, v.z * inv, v.w * inv);
    }
    __syncthreads();

    float val = 0.f;
    if (tid < K * K) {
        const int k1i = tid / K, k2i = tid % K;
        float dot = 0.f;
        #pragma unroll
        for (int c = 0; c < 64; ++c)
            dot += cen[(k1i << 6) + c] * cen[(k2i << 6) + c];
        val = (k1i == k2i) ? (1.0f - dot) : fmaxf(dot, 0.0f);
    }
    if (tid < 512) red[tid] = val;
    __syncthreads();
    #pragma unroll
    for (int off = 256; off > 0; off >>= 1) {
        if (tid < off) red[tid] += red[tid + off];
        __syncthreads();
    }
    if (tid == 0) out[0] = red[0] / 6859.0f;   // K^3
}

// ---------------------------------------------------------------------------
extern "C" void kernel_launch(void* const* d_in, const int* in_sizes, int n_in,
                              void* d_out, int out_size) {
    // Select pointers by element count (inputs: 134M, targets: 2M) — robust to order.
    int ii = 0, ti = 1;
    if (n_in >= 2 && in_sizes[1] > in_sizes[0]) { ii = 1; ti = 0; }
    const float* inp = (const float*)d_in[ii];
    const int* tgt32 = (const int*)d_in[ti];
    cudaFuncSetAttribute(k1_kernel, cudaFuncAttributeMaxDynamicSharedMemorySize, SMEM_BYTES);
    k1_kernel<<<GRID1, 640, SMEM_BYTES>>>(inp, tgt32);
    k2_kernel<<<153, 256>>>();
    k3_kernel<<<1, 640>>>((float*)d_out);
}

// round 12
// speedup vs baseline: 1.1827x; 1.1827x over previous
#include <cuda_runtime.h>
#include <math.h>
#include <stdint.h>

// Problem constants
#define HW      262144        // 512*512
#define NTILES  16384         // 2M pixels / 128-pixel tiles
#define GRID1   296           // 2 CTAs per SM
#define K       19
#define KC      1216          // 19*64

// Scratch (no allocation allowed -> __device__ globals)
__device__ float g_psums[GRID1 * KC];
__device__ int   g_pcnts[K * GRID1];     // [class][block]
__device__ float g_sums[KC];
__device__ int   g_cnt[K];

// K1 smem: channel row padded 512->528 B => consumer LDS.128 chunk index
// (33*ca + u) has phase-distinct octets (ca+u)&7 with NO swizzle, so linear
// 16B cp.async copies are directly consumable.
#define ROWB     528
#define LAB_OFF  (64*ROWB)               // labels area within stage
#define STAGE_B  (64*ROWB + 1024)        // 34816 B
#define NST      3
#define SM_SHIFT (NST*STAGE_B)           // dtype shift word
#define SMEM_BYTES (SM_SHIFT + 64)

__device__ __forceinline__ uint32_t s2u(const void* p) {
    uint32_t a;
    asm("{ .reg .u64 t; cvta.to.shared.u64 t, %1; cvt.u32.u64 %0, t; }" : "=r"(a) : "l"(p));
    return a;
}
#define CPA16(d,s) asm volatile("cp.async.cg.shared.global [%0], [%1], 16;" :: "r"(d), "l"(s) : "memory")
#define CPCOMMIT() asm volatile("cp.async.commit_group;" ::: "memory")
#define CPWAIT1()  asm volatile("cp.async.wait_group 1;" ::: "memory")

// ---------------------------------------------------------------------------
// K1: cp.async 3-stage pipeline + class-owned register accumulation.
//   warps 0..15: per tile issue 4x cp.async(16B) (channels w,w+16,w+32,w+48,
//     chunk q=lane) -> stage ring; ALSO consumers for classes 0..15.
//   warps 16..18: consumers only (classes 16..18).
//   warp 19: labels cp.async copier.
//   Per iteration: wait_group 1 -> ONE __syncthreads -> issue stage j+2
//   (always-commit; empty at tail) -> consume stage j (ballot label parse,
//   2x LDS.128 + predicated FADDs per matching quad).
// ---------------------------------------------------------------------------
__global__ __launch_bounds__(640, 2) void k1_kernel(const float* __restrict__ inp,
                                                    const int* __restrict__ tgt32) {
    extern __shared__ __align__(16) char smc[];
    const uint32_t base = s2u(smc);
    const int tid = threadIdx.x, lane = tid & 31, wid = tid >> 5, bid = blockIdx.x;
    const int nblk = (NTILES - bid + GRID1 - 1) / GRID1;
    const int q = lane, w = wid & 15;
    const bool is_loader = (wid < 16);
    const bool is_labw   = (wid == 19);

    if (is_labw && lane == 0) {   // dtype detect: int64 labels have zero high words
        int all0 = 1;
        #pragma unroll
        for (int i = 0; i < 32; ++i)
            if (tgt32[2 * i + 1] != 0) all0 = 0;
        *(int*)(smc + SM_SHIFT) = all0;
    }
    __syncthreads();
    const int shift = *(const int*)(smc + SM_SHIFT);

    // ---- prologue: issue tiles 0 and 1 into stages 0,1 (always 2 commits) ----
    #pragma unroll
    for (int jj = 0; jj < 2; ++jj) {
        if (jj < nblk) {
            const int t = bid + jj * GRID1;
            const int b = t >> 11, hw0 = (t & 2047) << 7;
            const uint32_t stg = base + jj * STAGE_B;
            if (is_loader) {
                const float* src = inp + ((size_t)b << 24) + hw0 + (size_t)w * HW + (q << 2);
                CPA16(stg + w * ROWB + q * 16,               src);
                CPA16(stg + (w + 16) * ROWB + q * 16, src + (size_t)16 * HW);
                CPA16(stg + (w + 32) * ROWB + q * 16, src + (size_t)32 * HW);
                CPA16(stg + (w + 48) * ROWB + q * 16, src + (size_t)48 * HW);
            } else if (is_labw) {
                const char* ls = (const char*)tgt32 + ((size_t)((b << 18) + hw0) << (2 + shift));
                CPA16(stg + LAB_OFF + lane * 16, ls + lane * 16);
                if (shift) CPA16(stg + LAB_OFF + 512 + lane * 16, ls + 512 + lane * 16);
            }
        }
        if (is_loader || is_labw) CPCOMMIT();
    }

    // ---- main loop ----
    float al = 0.f, al2 = 0.f, ah = 0.f, ah2 = 0.f;
    int ccnt = 0;
    for (int j = 0; j < nblk; ++j) {
        const int s = j - (j / NST) * NST;           // j % 3
        if (is_loader || is_labw) CPWAIT1();         // stage s (tile j) complete
        __syncthreads();                             // data visible to all
        // issue tile j+2 into stage (j+2)%3 (that stage was consumed in iter j-1)
        if (is_loader || is_labw) {
            const int j2 = j + 2;
            if (j2 < nblk) {
                const int s2 = j2 - (j2 / NST) * NST;
                const int t = bid + j2 * GRID1;
                const int b = t >> 11, hw0 = (t & 2047) << 7;
                const uint32_t stg = base + s2 * STAGE_B;
                if (is_loader) {
                    const float* src = inp + ((size_t)b << 24) + hw0 + (size_t)w * HW + (q << 2);
                    CPA16(stg + w * ROWB + q * 16,               src);
                    CPA16(stg + (w + 16) * ROWB + q * 16, src + (size_t)16 * HW);
                    CPA16(stg + (w + 32) * ROWB + q * 16, src + (size_t)32 * HW);
                    CPA16(stg + (w + 48) * ROWB + q * 16, src + (size_t)48 * HW);
                } else {
                    const char* ls = (const char*)tgt32 + ((size_t)((b << 18) + hw0) << (2 + shift));
                    CPA16(stg + LAB_OFF + lane * 16, ls + lane * 16);
                    if (shift) CPA16(stg + LAB_OFF + 512 + lane * 16, ls + 512 + lane * 16);
                }
            }
            CPCOMMIT();                              // always: uniform group count
        }
        // consume stage s: class warp wid
        if (wid < K) {
            const char* sp = smc + s * STAGE_B;
            int l0, l1, l2, l3;
            if (!shift) {
                int4 L = *(const int4*)(sp + LAB_OFF + lane * 16);
                l0 = L.x; l1 = L.y; l2 = L.z; l3 = L.w;
            } else {
                int4 A = *(const int4*)(sp + LAB_OFF + lane * 32);
                int4 B = *(const int4*)(sp + LAB_OFF + lane * 32 + 16);
                l0 = A.x; l1 = A.z; l2 = B.x; l3 = B.z;
            }
            const int e0 = (l0 == wid), e1 = (l1 == wid), e2 = (l2 == wid), e3 = (l3 == wid);
            const int mb = e0 | (e1 << 1) | (e2 << 2) | (e3 << 3);
            unsigned msk = __ballot_sync(0xffffffffu, mb != 0);
            ccnt += __reduce_add_sync(0xffffffffu, e0 + e1 + e2 + e3);
            const float* rlo = (const float*)(sp + lane * ROWB);
            const float* rhi = (const float*)(sp + (lane + 32) * ROWB);
            while (msk) {
                const int u = __ffs(msk) - 1; msk &= msk - 1;
                float4 flo = *(const float4*)(rlo + u * 4);
                float4 fhi = *(const float4*)(rhi + u * 4);
                const int m4 = __shfl_sync(0xffffffffu, mb, u);
                if (m4 & 1) { al  += flo.x; ah  += fhi.x; }
                if (m4 & 2) { al2 += flo.y; ah2 += fhi.y; }
                if (m4 & 4) { al  += flo.z; ah  += fhi.z; }
                if (m4 & 8) { al2 += flo.w; ah2 += fhi.w; }
            }
        }
    }

    // ---- write per-block partials ----
    if (wid < K) {
        g_psums[bid * KC + (wid << 6) + lane]      = al + al2;
        g_psums[bid * KC + (wid << 6) + 32 + lane] = ah + ah2;
        if (lane == 0) g_pcnts[wid * GRID1 + bid] = ccnt;
    }
}

// ---------------------------------------------------------------------------
// K2: wide psums reduce + counts. Blocks 0..151: 2 float4-columns each,
// 128 threads/column, coalesced rows + smem tree. Block 152: count reduce.
// ---------------------------------------------------------------------------
__global__ __launch_bounds__(256) void k2_kernel() {
    const int tid = threadIdx.x;
    if (blockIdx.x == 152) {      // counts: 8 warps over 19 classes
        const int wid = tid >> 5, lane = tid & 31;
        for (int cls = wid; cls < K; cls += 8) {
            int s = 0;
            for (int p = lane; p < GRID1; p += 32) s += g_pcnts[cls * GRID1 + p];
            #pragma unroll
            for (int off = 16; off > 0; off >>= 1) s += __shfl_xor_sync(0xffffffffu, s, off);
            if (lane == 0) g_cnt[cls] = s;
        }
        return;
    }
    __shared__ float4 red[256];
    const int half = tid >> 7;
    const int r    = tid & 127;
    const int col  = (blockIdx.x << 1) + half; // 0..303
    const float4* ps = (const float4*)g_psums;
    float4 s = make_float4(0.f, 0.f, 0.f, 0.f);
    for (int row = r; row < GRID1; row += 128) {
        float4 v = ps[row * 304 + col];
        s.x += v.x; s.y += v.y; s.z += v.z; s.w += v.w;
    }
    red[tid] = s;
    __syncthreads();
    #pragma unroll
    for (int off = 64; off > 0; off >>= 1) {
        if (r < off) {
            float4 o = red[tid + off];
            s.x += o.x; s.y += o.y; s.z += o.z; s.w += o.w;
            red[tid] = s;
        }
        __syncthreads();
    }
    if (r == 0) ((float4*)g_sums)[col] = red[half << 7];
}

// ---------------------------------------------------------------------------
// K3: centroids + norms (warp-per-class) + cosine-embedding loss. 1 block.
// ---------------------------------------------------------------------------
__global__ __launch_bounds__(640) void k3_kernel(float* __restrict__ out) {
    __shared__ float cen[KC];
    __shared__ float nrm[K];
    __shared__ int   cnts[K];
    __shared__ float red[512];
    const int tid = threadIdx.x;
    const int wid = tid >> 5, lane = tid & 31;

    if (tid < K) cnts[tid] = g_cnt[tid];
    __syncthreads();
    if (tid < 304) {
        float inv = 1.0f / fmaxf((float)cnts[tid >> 4], 1.0f);
        float4 v = ((const float4*)g_sums)[tid];
        ((float4*)cen)[tid] = make_float4(v.x * inv, v.y * inv, v.z * inv, v.w * inv);
    }
    __syncthreads();
    if (wid < K) {
        float x0 = cen[(wid << 6) + lane], x1 = cen[(wid << 6) + 32 + lane];
        float nn = x0 * x0 + x1 * x1;
        #pragma unroll
        for (int off = 16; off > 0; off >>= 1) nn += __shfl_xor_sync(0xffffffffu, nn, off);
        if (lane == 0) nrm[wid] = fmaxf(sqrtf(nn), 1e-8f);
    }
    __syncthreads();
    if (tid < 304) {
        float inv = 1.0f / nrm[tid >> 4];
        float4 v = ((const float4*)cen)[tid];
        ((float4*)cen)[tid] = make_float4(v.x * inv, v.y * inv, v.z * inv, v.w * inv);
    }
    __syncthreads();

    float val = 0.f;
    if (tid < K * K) {
        const int k1i = tid / K, k2i = tid % K;
        float dot = 0.f;
        #pragma unroll
        for (int c = 0; c < 64; ++c)
            dot += cen[(k1i << 6) + c] * cen[(k2i << 6) + c];
        val = (k1i == k2i) ? (1.0f - dot) : fmaxf(dot, 0.0f);
    }
    if (tid < 512) red[tid] = val;
    __syncthreads();
    #pragma unroll
    for (int off = 256; off > 0; off >>= 1) {
        if (tid < off) red[tid] += red[tid + off];
        __syncthreads();
    }
    if (tid == 0) out[0] = red[0] / 6859.0f;   // K^3
}

// ---------------------------------------------------------------------------
extern "C" void kernel_launch(void* const* d_in, const int* in_sizes, int n_in,
                              void* d_out, int out_size) {
    // Select pointers by element count (inputs: 134M, targets: 2M) — robust to order.
    int ii = 0, ti = 1;
    if (n_in >= 2 && in_sizes[1] > in_sizes[0]) { ii = 1; ti = 0; }
    const float* inp = (const float*)d_in[ii];
    const int* tgt32 = (const int*)d_in[ti];
    cudaFuncSetAttribute(k1_kernel, cudaFuncAttributeMaxDynamicSharedMemorySize, SMEM_BYTES);
    k1_kernel<<<GRID1, 640, SMEM_BYTES>>>(inp, tgt32);
    k2_kernel<<<153, 256>>>();
    k3_kernel<<<1, 640>>>((float*)d_out);
}

// round 15
// speedup vs baseline: 1.5034x; 1.2711x over previous
#include <cuda_runtime.h>
#include <math.h>

// Problem constants
#define HW      262144        // 512*512
#define NTILES  16384         // 2M pixels / 128-pixel tiles
#define GRID1   296           // 2 * 148 SMs
#define K       19
#define KC      1216          // 19*64

// Scratch (no allocation allowed -> __device__ globals)
__device__ float g_psums[GRID1 * KC];
__device__ int   g_pcnts[K * GRID1];     // [class][block]
__device__ float g_sums[KC];
__device__ int   g_cnt[K];

#define TILE_F   8192
// dyn smem: 2 tiles + order[2][128] + bstart/bcnt/bcur[2][19]
#define SMEM_BYTES (2*TILE_F*4 + 2*128*4 + 3*2*19*4 + 64)

// ---------------------------------------------------------------------------
// K1: streaming centroid scatter-sum, class-owned register accumulation,
// double-buffered single-barrier pipeline. (R6/R8 version — best measured:
// 87.3-87.5us, DRAM 79%. Structural alternatives all measured slower:
// work-stealing 94.4, warp-specialized ring 122.9, bulk-async 134.6,
// cp.async 112.7.)
// ---------------------------------------------------------------------------
__global__ __launch_bounds__(640, 2) void k1_kernel(const float* __restrict__ inp,
                                                    const int* __restrict__ tgt32) {
    extern __shared__ float sm[];
    float* tiles  = sm;                        // [2][8192]
    int*   order  = (int*)(sm + 2 * TILE_F);   // [2][128]
    int*   bstart = order + 256;               // [2][19]
    int*   bcnt   = bstart + 38;               // [2][19]
    int*   bcur   = bcnt + 38;                 // [2][19]

    const int tid  = threadIdx.x;
    const int lane = tid & 31;
    const int wid  = tid >> 5;
    const int bid  = blockIdx.x;

    // loader mapping (tid < 512): q = pixel-quad, channel pairs (w,32+w),(16+w,48+w)
    const int q = tid & 31, w = (tid >> 5) & 15;
    const int c0 = w, c1 = 16 + w, c2 = 32 + w, c3 = 48 + w;
    const int slot0 = 2 * (w ^ q);
    const int slot1 = 2 * ((w ^ q) ^ 16);

    float a0 = 0.f, a1 = 0.f, b0 = 0.f, b1 = 0.f;
    int   ccnt = 0;
    float4 v0, v1, v2, v3;
    int   lab0 = 0, lab1 = 0, lab2 = 0, lab3 = 0;
    int   shift = 0;

    int t = bid, par = 0;

    // ---- prologue: prefetch tile bid (data + labels), detect targets dtype ----
    {
        const int b = t >> 11, hw0 = (t & 2047) << 7;
        if (tid < 512) {
            const float* p = inp + ((size_t)b << 24) + hw0 + (q << 2);
            v0 = __ldcs((const float4*)(p + (size_t)c0 * HW));
            v1 = __ldcs((const float4*)(p + (size_t)c1 * HW));
            v2 = __ldcs((const float4*)(p + (size_t)c2 * HW));
            v3 = __ldcs((const float4*)(p + (size_t)c3 * HW));
        }
        if (wid == 19) {
            // int64 labels 0..18 have all-zero high words; int32 ~never does
            if (lane == 0) {
                int all0 = 1;
                #pragma unroll
                for (int i = 0; i < 32; ++i)
                    if (tgt32[2 * i + 1] != 0) all0 = 0;
                shift = all0;
            }
            shift = __shfl_sync(0xffffffffu, shift, 0);
            const int tb = (b << 18) + hw0;
            lab0 = tgt32[(size_t)(tb + lane)       << shift];
            lab1 = tgt32[(size_t)(tb + lane +  32) << shift];
            lab2 = tgt32[(size_t)(tb + lane +  64) << shift];
            lab3 = tgt32[(size_t)(tb + lane +  96) << shift];
        }
    }

    bool first = true;
    while (true) {
        __syncthreads();
        const bool store = (t < NTILES);
        if (store) {
            if (tid < 512) {   // STS.64, conflict-free
                float* r = tiles + par * TILE_F + (q << 8);
                *(float2*)(r +       slot0) = make_float2(v0.x, v2.x);
                *(float2*)(r +  64 + slot0) = make_float2(v0.y, v2.y);
                *(float2*)(r + 128 + slot0) = make_float2(v0.z, v2.z);
                *(float2*)(r + 192 + slot0) = make_float2(v0.w, v2.w);
                *(float2*)(r +       slot1) = make_float2(v1.x, v3.x);
                *(float2*)(r +  64 + slot1) = make_float2(v1.y, v3.y);
                *(float2*)(r + 128 + slot1) = make_float2(v1.z, v3.z);
                *(float2*)(r + 192 + slot1) = make_float2(v1.w, v3.w);
            } else if (wid == 19) {   // counting sort of 128 labels -> meta[par]
                int* bc = bcnt + par * 19;
                int* bs = bstart + par * 19;
                int* bu = bcur + par * 19;
                int* od = order + par * 128;
                int l0 = min(max(lab0, 0), 18), l1 = min(max(lab1, 0), 18);
                int l2 = min(max(lab2, 0), 18), l3 = min(max(lab3, 0), 18);
                if (lane < 19) bc[lane] = 0;
                __syncwarp();
                atomicAdd(&bc[l0], 1); atomicAdd(&bc[l1], 1);
                atomicAdd(&bc[l2], 1); atomicAdd(&bc[l3], 1);
                __syncwarp();
                int c = (lane < 19) ? bc[lane] : 0;
                int x = c;
                #pragma unroll
                for (int off = 1; off < 32; off <<= 1) {
                    int y = __shfl_up_sync(0xffffffffu, x, off);
                    if (lane >= off) x += y;
                }
                if (lane < 19) { bs[lane] = x - c; bu[lane] = x - c; }
                __syncwarp();
                int p0 = atomicAdd(&bu[l0], 1); od[p0] = lane;
                int p1 = atomicAdd(&bu[l1], 1); od[p1] = lane + 32;
                int p2 = atomicAdd(&bu[l2], 1); od[p2] = lane + 64;
                int p3 = atomicAdd(&bu[l3], 1); od[p3] = lane + 96;
            }
        }
        const int nt = t + GRID1;
        if (nt < NTILES) {   // prefetch next tile (latency spans full iteration)
            const int nb = nt >> 11, nh = (nt & 2047) << 7;
            if (tid < 512) {
                const float* p = inp + ((size_t)nb << 24) + nh + (q << 2);
                v0 = __ldcs((const float4*)(p + (size_t)c0 * HW));
                v1 = __ldcs((const float4*)(p + (size_t)c1 * HW));
                v2 = __ldcs((const float4*)(p + (size_t)c2 * HW));
                v3 = __ldcs((const float4*)(p + (size_t)c3 * HW));
            } else if (wid == 19) {
                const int tb = (nb << 18) + nh;
                lab0 = tgt32[(size_t)(tb + lane)       << shift];
                lab1 = tgt32[(size_t)(tb + lane +  32) << shift];
                lab2 = tgt32[(size_t)(tb + lane +  64) << shift];
                lab3 = tgt32[(size_t)(tb + lane +  96) << shift];
            }
        }
        // accumulate previous tile from buf[par^1] (register accumulators)
        if (!first && wid < K) {
            const int pp   = par ^ 1;
            const int base = bstart[pp * 19 + wid];
            const int n    = bcnt[pp * 19 + wid];
            const int* od  = order + pp * 128;
            const float* tb = tiles + pp * TILE_F;
            ccnt += n;
            int i = 0;
            for (; i + 2 <= n; i += 2) {   // two independent chains
                const int pA = od[base + i], pB = od[base + i + 1];
                float2 fA = *(const float2*)(tb + (pA << 6) + 2 * (lane ^ ((pA >> 2) & 31)));
                float2 fB = *(const float2*)(tb + (pB << 6) + 2 * (lane ^ ((pB >> 2) & 31)));
                a0 += fA.x; a1 += fA.y;
                b0 += fB.x; b1 += fB.y;
            }
            if (i < n) {
                const int pA = od[base + i];
                float2 fA = *(const float2*)(tb + (pA << 6) + 2 * (lane ^ ((pA >> 2) & 31)));
                a0 += fA.x; a1 += fA.y;
            }
        }
        first = false;
        if (!store) break;     // post-last iteration: final accumulate done
        t = nt; par ^= 1;
    }

    // ---- write per-block partials ----
    if (wid < K) {
        g_psums[bid * KC + (wid << 6) + lane]      = a0 + b0;
        g_psums[bid * KC + (wid << 6) + 32 + lane] = a1 + b1;
        if (lane == 0) g_pcnts[wid * GRID1 + bid] = ccnt;
    }
}

// ---------------------------------------------------------------------------
// K2: wide psums reduce + counts. Blocks 0..151: 2 float4-columns each,
// 128 threads/column, coalesced rows + smem tree. Block 152: count reduce.
// ---------------------------------------------------------------------------
__global__ __launch_bounds__(256) void k2_kernel() {
    const int tid = threadIdx.x;
    if (blockIdx.x == 152) {      // counts: 8 warps over 19 classes
        const int wid = tid >> 5, lane = tid & 31;
        for (int cls = wid; cls < K; cls += 8) {
            int s = 0;
            for (int p = lane; p < GRID1; p += 32) s += g_pcnts[cls * GRID1 + p];
            #pragma unroll
            for (int off = 16; off > 0; off >>= 1) s += __shfl_xor_sync(0xffffffffu, s, off);
            if (lane == 0) g_cnt[cls] = s;
        }
        return;
    }
    __shared__ float4 red[256];
    const int half = tid >> 7;                 // which of the 2 columns
    const int r    = tid & 127;                // row lane within column
    const int col  = (blockIdx.x << 1) + half; // 0..303
    const float4* ps = (const float4*)g_psums;
    float4 s = make_float4(0.f, 0.f, 0.f, 0.f);
    for (int row = r; row < GRID1; row += 128) {
        float4 v = ps[row * 304 + col];
        s.x += v.x; s.y += v.y; s.z += v.z; s.w += v.w;
    }
    red[tid] = s;
    __syncthreads();
    #pragma unroll
    for (int off = 64; off > 0; off >>= 1) {
        if (r < off) {
            float4 o = red[tid + off];
            s.x += o.x; s.y += o.y; s.z += o.z; s.w += o.w;
            red[tid] = s;
        }
        __syncthreads();
    }
    if (r == 0) ((float4*)g_sums)[col] = red[half << 7];
}

// ---------------------------------------------------------------------------
// K3: centroids + norms (warp-per-class) + cosine-embedding loss. 1 block.
// ---------------------------------------------------------------------------
__global__ __launch_bounds__(640) void k3_kernel(float* __restrict__ out) {
    __shared__ float cen[KC];
    __shared__ float nrm[K];
    __shared__ int   cnts[K];
    __shared__ float red[512];
    const int tid = threadIdx.x;
    const int wid = tid >> 5, lane = tid & 31;

    if (tid < K) cnts[tid] = g_cnt[tid];
    __syncthreads();
    if (tid < 304) {   // float4 load + centroid divide (16 float4 per class)
        float inv = 1.0f / fmaxf((float)cnts[tid >> 4], 1.0f);
        float4 v = ((const float4*)g_sums)[tid];
        ((float4*)cen)[tid] = make_float4(v.x * inv, v.y * inv, v.z * inv, v.w * inv);
    }
    __syncthreads();
    if (wid < K) {     // warp per class: 2 elems/lane + shfl tree
        float x0 = cen[(wid << 6) + lane], x1 = cen[(wid << 6) + 32 + lane];
        float nn = x0 * x0 + x1 * x1;
        #pragma unroll
        for (int off = 16; off > 0; off >>= 1) nn += __shfl_xor_sync(0xffffffffu, nn, off);
        if (lane == 0) nrm[wid] = fmaxf(sqrtf(nn), 1e-8f);
    }
    __syncthreads();
    if (tid < 304) {
        float inv = 1.0f / nrm[tid >> 4];
        float4 v = ((const float4*)cen)[tid];
        ((float4*)cen)[tid] = make_float4(v.x * inv, v.y * inv, v.z * inv, v.w * inv);
    }
    __syncthreads();

    float val = 0.f;
    if (tid < K * K) {
        const int k1i = tid / K, k2i = tid % K;
        float dot = 0.f;
        #pragma unroll
        for (int c = 0; c < 64; ++c)
            dot += cen[(k1i << 6) + c] * cen[(k2i << 6) + c];
        val = (k1i == k2i) ? (1.0f - dot) : fmaxf(dot, 0.0f);
    }
    if (tid < 512) red[tid] = val;
    __syncthreads();
    #pragma unroll
    for (int off = 256; off > 0; off >>= 1) {
        if (tid < off) red[tid] += red[tid + off];
        __syncthreads();
    }
    if (tid == 0) out[0] = red[0] / 6859.0f;   // K^3
}

// ---------------------------------------------------------------------------
extern "C" void kernel_launch(void* const* d_in, const int* in_sizes, int n_in,
                              void* d_out, int out_size) {
    // Select pointers by element count (inputs: 134M, targets: 2M) — robust to order.
    int ii = 0, ti = 1;
    if (n_in >= 2 && in_sizes[1] > in_sizes[0]) { ii = 1; ti = 0; }
    const float* inp = (const float*)d_in[ii];
    const int* tgt32 = (const int*)d_in[ti];
    cudaFuncSetAttribute(k1_kernel, cudaFuncAttributeMaxDynamicSharedMemorySize, SMEM_BYTES);
    k1_kernel<<<GRID1, 640, SMEM_BYTES>>>(inp, tgt32);
    k2_kernel<<<153, 256>>>();
    k3_kernel<<<1, 640>>>((float*)d_out);
}